// round 2
// baseline (speedup 1.0000x reference)
#include <cuda_runtime.h>
#include <cuda_bf16.h>
#include <cstdint>

// HashGridEncoding: P points x L=9 levels, dense multi-res grid, trilinear.
// L1-wavefront-bound (ncu R1: l1tex 80.4%). Optimization: merge each x-corner
// pair (q[f], q[f+1]) into one aligned LDG.128 at f>>1 (even f: 1 wavefront
// instead of 2; odd f: predicated second LDG.128). Table is 9*2^21 entries;
// max flat index ~16.9M, so the +1 float4 never goes OOB.

#define NUM_LEVELS 9

// Load the x-pair (q[b], q[b+1]) using aligned float4 loads.
__device__ __forceinline__ void load_pair(const float4* __restrict__ t4, int b,
                                          float2& q0, float2& q1)
{
    int a = b >> 1;
    float4 qa = __ldg(t4 + a);
    if (b & 1) {
        float4 qb = __ldg(t4 + a + 1);       // predicated: odd lanes only
        q0 = make_float2(qa.z, qa.w);
        q1 = make_float2(qb.x, qb.y);
    } else {
        q0 = make_float2(qa.x, qa.y);
        q1 = make_float2(qa.z, qa.w);
    }
}

__global__ void __launch_bounds__(288) hashgrid_kernel(
    const float* __restrict__ x,
    const float* __restrict__ table,
    float* __restrict__ out,
    int P)
{
    __shared__ float sx[96];                 // 32 points * 3 coords
    int pbase = blockIdx.x * 32;

    // Stage point coords once per block (coalesced), instead of 9x redundant
    // per-thread loads.
    if (threadIdx.x < 96) {
        int gidx = pbase * 3 + threadIdx.x;
        sx[threadIdx.x] = (gidx < P * 3) ? x[gidx] : 0.0f;
    }
    __syncthreads();

    int p_local = threadIdx.x / NUM_LEVELS;
    int l       = threadIdx.x - p_local * NUM_LEVELS;
    int p = pbase + p_local;
    if (p >= P || threadIdx.x >= 288) return;

    float px = sx[p_local * 3 + 0];
    float py = sx[p_local * 3 + 1];
    float pz = sx[p_local * 3 + 2];

    int   vi = 1 << l;
    float vf = (float)vi;

    float gx = (px + 1.0f) * 0.5f * vf;
    float gy = (py + 1.0f) * 0.5f * vf;
    float gz = (pz + 1.0f) * 0.5f * vf;

    float bxf = floorf(gx);
    float byf = floorf(gy);
    float bzf = floorf(gz);

    float fx = gx - bxf;
    float fy = gy - byf;
    float fz = gz - bzf;

    int ix = (int)bxf;
    int iy = (int)byf;
    int iz = (int)bzf;

    int flat = ix + iy * vi + iz * vi * vi;
    int dz   = vi * vi;

    const float4* __restrict__ tab4 = (const float4*)table;

    // 4 x-pairs at bases {flat, flat+vi, flat+dz, flat+dz+vi}
    float2 q000, q100, q010, q110, q001, q101, q011, q111;
    load_pair(tab4, flat,           q000, q100);
    load_pair(tab4, flat + vi,      q010, q110);
    load_pair(tab4, flat + dz,      q001, q101);
    load_pair(tab4, flat + dz + vi, q011, q111);

    float wx0 = 1.0f - fx, wx1 = fx;
    float wy0 = 1.0f - fy, wy1 = fy;
    float wz0 = 1.0f - fz, wz1 = fz;

    float a0x = wx0 * q000.x + wx1 * q100.x;
    float a0y = wx0 * q000.y + wx1 * q100.y;
    float a1x = wx0 * q010.x + wx1 * q110.x;
    float a1y = wx0 * q010.y + wx1 * q110.y;
    float a2x = wx0 * q001.x + wx1 * q101.x;
    float a2y = wx0 * q001.y + wx1 * q101.y;
    float a3x = wx0 * q011.x + wx1 * q111.x;
    float a3y = wx0 * q011.y + wx1 * q111.y;

    float b0x = wy0 * a0x + wy1 * a1x;
    float b0y = wy0 * a0y + wy1 * a1y;
    float b1x = wy0 * a2x + wy1 * a3x;
    float b1y = wy0 * a2y + wy1 * a3y;

    float rx = wz0 * b0x + wz1 * b1x;
    float ry = wz0 * b0y + wz1 * b1y;

    float2* __restrict__ o2 = (float2*)out;
    o2[p * NUM_LEVELS + l] = make_float2(rx, ry);
}

extern "C" void kernel_launch(void* const* d_in, const int* in_sizes, int n_in,
                              void* d_out, int out_size)
{
    const float* x     = (const float*)d_in[0];
    const float* table = (const float*)d_in[1];
    float* out         = (float*)d_out;

    int P = in_sizes[0] / 3;
    int blocks = (P + 31) / 32;        // 32 points per block, 288 threads
    hashgrid_kernel<<<blocks, 288>>>(x, table, out, P);
}